// round 1
// baseline (speedup 1.0000x reference)
#include <cuda_runtime.h>

#define TPB 256
#define HD 64
#define NV 16

typedef unsigned long long u64;

// Packed f32x2 helpers (sm_100a). ptxas will not auto-fuse these; inline PTX required.
__device__ __forceinline__ u64 pk2(float x, float y) {
    u64 r;
    asm("mov.b64 %0, {%1, %2};" : "=l"(r) : "f"(x), "f"(y));
    return r;
}
__device__ __forceinline__ void upk2(u64 v, float& x, float& y) {
    asm("mov.b64 {%0, %1}, %2;" : "=f"(x), "=f"(y) : "l"(v));
}
__device__ __forceinline__ u64 f2fma(u64 a, u64 b, u64 c) {
    u64 d;
    asm("fma.rn.f32x2 %0, %1, %2, %3;" : "=l"(d) : "l"(a), "l"(b), "l"(c));
    return d;
}

__global__ __launch_bounds__(TPB)
void ncm_chain_kernel(
    const float* __restrict__ noise,      // [V, N]
    const float* __restrict__ stds,       // [V]
    const float* __restrict__ w0_1,       // [1, 64]
    const float* __restrict__ b0_1,       // [64]
    const float* __restrict__ w0_2,       // [64, 64]
    const float* __restrict__ b0_2,       // [64]
    const float* __restrict__ w0_3,       // [64, 1]
    const float* __restrict__ b0_3,       // [1]
    const float* __restrict__ W1,         // [V-1, 2, 64]
    const float* __restrict__ B1,         // [V-1, 64]
    const float* __restrict__ W2,         // [V-1, 64, 64]
    const float* __restrict__ B2,         // [V-1, 64]
    const float* __restrict__ W3,         // [V-1, 64, 1]
    const float* __restrict__ B3,         // [V-1, 1]
    float* __restrict__ out,              // [V, N]
    int nsamp)
{
    __shared__ __align__(16) float sW2[HD * HD];  // 16 KB, current variable's hidden weights
    __shared__ float sWs[HD];   // layer1 weight on carry (zeros for v=0)
    __shared__ float sWe[HD];   // layer1 weight on noise
    __shared__ float sB1[HD];
    __shared__ float sB2[HD];
    __shared__ float sW3[HD];
    __shared__ float sB3;
    __shared__ float sStd[NV];

    const int tid = threadIdx.x;
    const long long n = (long long)blockIdx.x * TPB + tid;
    const bool active = (n < (long long)nsamp);

    if (tid < NV) sStd[tid] = fabsf(stds[tid]);

    float carry = 0.0f;

    for (int v = 0; v < NV; v++) {
        __syncthreads();  // previous iteration's compute must finish before reload

        // ---- stage this variable's weights into shared ----
        const float *pw2, *pwe, *pws, *pb1, *pb2, *pw3, *pb3;
        if (v == 0) {
            pws = 0; pwe = w0_1; pb1 = b0_1;
            pw2 = w0_2; pb2 = b0_2; pw3 = w0_3; pb3 = b0_3;
        } else {
            pws = W1 + (long long)(v - 1) * 2 * HD;
            pwe = pws + HD;
            pb1 = B1 + (long long)(v - 1) * HD;
            pw2 = W2 + (long long)(v - 1) * HD * HD;
            pb2 = B2 + (long long)(v - 1) * HD;
            pw3 = W3 + (long long)(v - 1) * HD;
            pb3 = B3 + (v - 1);
        }
        for (int k = tid; k < (HD * HD) / 4; k += TPB) {
            ((float4*)sW2)[k] = ((const float4*)pw2)[k];
        }
        if (tid < HD) {
            sWs[tid] = (v == 0) ? 0.0f : pws[tid];
            sWe[tid] = pwe[tid];
            sB1[tid] = pb1[tid];
            sB2[tid] = pb2[tid];
            sW3[tid] = pw3[tid];
        }
        if (tid == 0) sB3 = pb3[0];
        __syncthreads();

        // ---- per-sample MLP ----
        const float e = active ? noise[(long long)v * nsamp + n] * sStd[v] : 0.0f;
        const float s = carry;

        // layer 1: h1[i] = relu(s*Ws[i] + e*We[i] + B1[i]), stored as duplicated f32x2
        u64 h1[HD];
        #pragma unroll
        for (int i = 0; i < HD; i++) {
            float h = fmaf(s, sWs[i], fmaf(e, sWe[i], sB1[i]));
            h = fmaxf(h, 0.0f);
            h1[i] = pk2(h, h);
        }

        // layers 2+3 fused: for each group of 4 output columns, dot(h1, W2[:,j]),
        // relu, scale by W3[j] into the scalar carry accumulator.
        float sacc = sB3;
        for (int jp = 0; jp < HD / 4; jp++) {
            u64 a01 = pk2(sB2[jp * 4 + 0], sB2[jp * 4 + 1]);
            u64 a23 = pk2(sB2[jp * 4 + 2], sB2[jp * 4 + 3]);
            const char* base = (const char*)(sW2 + jp * 4);
            #pragma unroll
            for (int i = 0; i < HD; i++) {
                // one LDS.128: {W2[i][4jp], W2[i][4jp+1], W2[i][4jp+2], W2[i][4jp+3]}
                ulonglong2 w = *(const ulonglong2*)(base + (size_t)i * (HD * sizeof(float)));
                a01 = f2fma(h1[i], w.x, a01);
                a23 = f2fma(h1[i], w.y, a23);
            }
            float a0, a1, a2, a3;
            upk2(a01, a0, a1);
            upk2(a23, a2, a3);
            sacc = fmaf(fmaxf(a0, 0.0f), sW3[jp * 4 + 0], sacc);
            sacc = fmaf(fmaxf(a1, 0.0f), sW3[jp * 4 + 1], sacc);
            sacc = fmaf(fmaxf(a2, 0.0f), sW3[jp * 4 + 2], sacc);
            sacc = fmaf(fmaxf(a3, 0.0f), sW3[jp * 4 + 3], sacc);
        }

        carry = sacc;
        if (active) out[(long long)v * nsamp + n] = sacc;
    }
}

extern "C" void kernel_launch(void* const* d_in, const int* in_sizes, int n_in,
                              void* d_out, int out_size) {
    const float* noise = (const float*)d_in[0];
    const float* stds  = (const float*)d_in[1];
    const float* w0_1  = (const float*)d_in[2];
    const float* b0_1  = (const float*)d_in[3];
    const float* w0_2  = (const float*)d_in[4];
    const float* b0_2  = (const float*)d_in[5];
    const float* w0_3  = (const float*)d_in[6];
    const float* b0_3  = (const float*)d_in[7];
    const float* W1    = (const float*)d_in[8];
    const float* B1    = (const float*)d_in[9];
    const float* W2    = (const float*)d_in[10];
    const float* B2    = (const float*)d_in[11];
    const float* W3    = (const float*)d_in[12];
    const float* B3    = (const float*)d_in[13];

    const int nsamp = in_sizes[0] / NV;   // noise is [V, N, 1]
    const int grid = (nsamp + TPB - 1) / TPB;

    ncm_chain_kernel<<<grid, TPB>>>(noise, stds,
                                    w0_1, b0_1, w0_2, b0_2, w0_3, b0_3,
                                    W1, B1, W2, B2, W3, B3,
                                    (float*)d_out, nsamp);
}

// round 2
// speedup vs baseline: 1.1823x; 1.1823x over previous
#include <cuda_runtime.h>

#define TPB 256
#define HD 64
#define NV 16
#define S 2   // samples per thread

typedef unsigned long long u64;

// Packed f32x2 helpers (sm_100a). ptxas will not auto-fuse; inline PTX required.
__device__ __forceinline__ u64 pk2(float x, float y) {
    u64 r;
    asm("mov.b64 %0, {%1, %2};" : "=l"(r) : "f"(x), "f"(y));
    return r;
}
__device__ __forceinline__ void upk2(u64 v, float& x, float& y) {
    asm("mov.b64 {%0, %1}, %2;" : "=f"(x), "=f"(y) : "l"(v));
}
__device__ __forceinline__ u64 f2fma(u64 a, u64 b, u64 c) {
    u64 d;
    asm("fma.rn.f32x2 %0, %1, %2, %3;" : "=l"(d) : "l"(a), "l"(b), "l"(c));
    return d;
}

__global__ __launch_bounds__(TPB, 1)
void ncm_chain_kernel(
    const float* __restrict__ noise,      // [V, N]
    const float* __restrict__ stds,       // [V]
    const float* __restrict__ w0_1, const float* __restrict__ b0_1,
    const float* __restrict__ w0_2, const float* __restrict__ b0_2,
    const float* __restrict__ w0_3, const float* __restrict__ b0_3,
    const float* __restrict__ W1,   const float* __restrict__ B1,
    const float* __restrict__ W2,   const float* __restrict__ B2,
    const float* __restrict__ W3,   const float* __restrict__ B3,
    float* __restrict__ out,              // [V, N]
    int nsamp)
{
    __shared__ __align__(16) float sW2[HD * HD];  // 16 KB, row-major [i][j]
    __shared__ float sWs[HD];   // layer1 weight on carry (zeros for v=0)
    __shared__ float sWe[HD];   // layer1 weight on noise
    __shared__ float sB1[HD];
    __shared__ float sB2[HD];
    __shared__ float sW3[HD];
    __shared__ float sB3;
    __shared__ float sStd[NV];

    const int tid = threadIdx.x;
    const long long nbase = (long long)blockIdx.x * (TPB * S) + tid;

    if (tid < NV) sStd[tid] = fabsf(stds[tid]);

    float carry[S];
    bool active[S];
    #pragma unroll
    for (int s = 0; s < S; s++) {
        carry[s] = 0.0f;
        active[s] = (nbase + s * TPB) < (long long)nsamp;
    }

    for (int v = 0; v < NV; v++) {
        __syncthreads();  // previous iteration's compute done before reload

        // ---- stage this variable's weights into shared ----
        const float *pw2, *pwe, *pws, *pb1, *pb2, *pw3, *pb3;
        if (v == 0) {
            pws = 0; pwe = w0_1; pb1 = b0_1;
            pw2 = w0_2; pb2 = b0_2; pw3 = w0_3; pb3 = b0_3;
        } else {
            pws = W1 + (long long)(v - 1) * 2 * HD;
            pwe = pws + HD;
            pb1 = B1 + (long long)(v - 1) * HD;
            pw2 = W2 + (long long)(v - 1) * HD * HD;
            pb2 = B2 + (long long)(v - 1) * HD;
            pw3 = W3 + (long long)(v - 1) * HD;
            pb3 = B3 + (v - 1);
        }
        for (int k = tid; k < (HD * HD) / 4; k += TPB) {
            ((float4*)sW2)[k] = ((const float4*)pw2)[k];
        }
        if (tid < HD) {
            sWs[tid] = (v == 0) ? 0.0f : pws[tid];
            sWe[tid] = pwe[tid];
            sB1[tid] = pb1[tid];
            sB2[tid] = pb2[tid];
            sW3[tid] = pw3[tid];
        }
        if (tid == 0) sB3 = pb3[0];
        __syncthreads();

        // ---- per-sample noise ----
        float e[S];
        #pragma unroll
        for (int s = 0; s < S; s++) {
            e[s] = active[s] ? noise[(long long)v * nsamp + nbase + s * TPB] * sStd[v]
                             : 0.0f;
        }

        // ---- 64 j-accumulators per sample, packed as 32 f32x2 ----
        // acc[s][2*jp] holds columns {4jp, 4jp+1}; acc[s][2*jp+1] holds {4jp+2, 4jp+3}
        u64 acc[S][HD / 2];
        #pragma unroll
        for (int jp = 0; jp < HD / 4; jp++) {
            u64 b01 = pk2(sB2[jp * 4 + 0], sB2[jp * 4 + 1]);
            u64 b23 = pk2(sB2[jp * 4 + 2], sB2[jp * 4 + 3]);
            #pragma unroll
            for (int s = 0; s < S; s++) {
                acc[s][2 * jp]     = b01;
                acc[s][2 * jp + 1] = b23;
            }
        }

        // ---- main loop: i outer, h computed on the fly, W2 row broadcast ----
        #pragma unroll 4
        for (int i = 0; i < HD; i++) {
            u64 hd[S];
            #pragma unroll
            for (int s = 0; s < S; s++) {
                float h = fmaf(carry[s], sWs[i], fmaf(e[s], sWe[i], sB1[i]));
                h = fmaxf(h, 0.0f);
                hd[s] = pk2(h, h);
            }
            const ulonglong2* wrow = (const ulonglong2*)(sW2 + i * HD);
            #pragma unroll
            for (int jp = 0; jp < HD / 4; jp++) {
                ulonglong2 w = wrow[jp];   // LDS.128 broadcast: cols 4jp..4jp+3 of row i
                #pragma unroll
                for (int s = 0; s < S; s++) {
                    acc[s][2 * jp]     = f2fma(hd[s], w.x, acc[s][2 * jp]);
                    acc[s][2 * jp + 1] = f2fma(hd[s], w.y, acc[s][2 * jp + 1]);
                }
            }
        }

        // ---- epilogue: relu(h2) dot W3 + b3 -> carry ----
        #pragma unroll
        for (int s = 0; s < S; s++) {
            float sacc = sB3;
            #pragma unroll
            for (int jp = 0; jp < HD / 4; jp++) {
                float a0, a1, a2, a3;
                upk2(acc[s][2 * jp],     a0, a1);
                upk2(acc[s][2 * jp + 1], a2, a3);
                sacc = fmaf(fmaxf(a0, 0.0f), sW3[jp * 4 + 0], sacc);
                sacc = fmaf(fmaxf(a1, 0.0f), sW3[jp * 4 + 1], sacc);
                sacc = fmaf(fmaxf(a2, 0.0f), sW3[jp * 4 + 2], sacc);
                sacc = fmaf(fmaxf(a3, 0.0f), sW3[jp * 4 + 3], sacc);
            }
            carry[s] = sacc;
            if (active[s]) out[(long long)v * nsamp + nbase + s * TPB] = sacc;
        }
    }
}

extern "C" void kernel_launch(void* const* d_in, const int* in_sizes, int n_in,
                              void* d_out, int out_size) {
    const float* noise = (const float*)d_in[0];
    const float* stds  = (const float*)d_in[1];
    const float* w0_1  = (const float*)d_in[2];
    const float* b0_1  = (const float*)d_in[3];
    const float* w0_2  = (const float*)d_in[4];
    const float* b0_2  = (const float*)d_in[5];
    const float* w0_3  = (const float*)d_in[6];
    const float* b0_3  = (const float*)d_in[7];
    const float* W1    = (const float*)d_in[8];
    const float* B1    = (const float*)d_in[9];
    const float* W2    = (const float*)d_in[10];
    const float* B2    = (const float*)d_in[11];
    const float* W3    = (const float*)d_in[12];
    const float* B3    = (const float*)d_in[13];

    const int nsamp = in_sizes[0] / NV;   // noise is [V, N, 1]
    const int grid = (nsamp + TPB * S - 1) / (TPB * S);

    ncm_chain_kernel<<<grid, TPB>>>(noise, stds,
                                    w0_1, b0_1, w0_2, b0_2, w0_3, b0_3,
                                    W1, B1, W2, B2, W3, B3,
                                    (float*)d_out, nsamp);
}

// round 4
// speedup vs baseline: 2.8235x; 2.3881x over previous
#include <cuda_runtime.h>
#include <cuda_bf16.h>
#include <cstdint>

#define HD   64
#define NV   16
#define TPB  128   // threads per CTA = samples per CTA (M)

// ---------------- helpers ----------------
__device__ __forceinline__ uint32_t smem_u32(const void* p) {
    uint32_t a;
    asm("{ .reg .u64 t; cvta.to.shared.u64 t, %1; cvt.u32.u64 %0, t; }" : "=r"(a) : "l"(p));
    return a;
}
__device__ __forceinline__ void ldmx4(uint32_t& r0, uint32_t& r1, uint32_t& r2, uint32_t& r3,
                                      uint32_t addr) {
    asm volatile("ldmatrix.sync.aligned.m8n8.x4.shared.b16 {%0,%1,%2,%3}, [%4];"
                 : "=r"(r0), "=r"(r1), "=r"(r2), "=r"(r3) : "r"(addr));
}
__device__ __forceinline__ void mma_bf16(float& c0, float& c1, float& c2, float& c3,
                                         uint32_t a0, uint32_t a1, uint32_t a2, uint32_t a3,
                                         uint32_t b0, uint32_t b1) {
    asm volatile("mma.sync.aligned.m16n8k16.row.col.f32.bf16.bf16.f32 "
                 "{%0,%1,%2,%3}, {%4,%5,%6,%7}, {%8,%9}, {%0,%1,%2,%3};"
                 : "+f"(c0), "+f"(c1), "+f"(c2), "+f"(c3)
                 : "r"(a0), "r"(a1), "r"(a2), "r"(a3), "r"(b0), "r"(b1));
}
// split x into bf16 hi + fp32 residual; pack pairs
__device__ __forceinline__ uint32_t split_hi_pair(float h0, float h1, float& l0, float& l1) {
    uint32_t hp;
    asm("{ .reg .b16 x, y; .reg .f32 r0, r1;\n\t"
        "cvt.rn.bf16.f32 x, %3;\n\t"
        "cvt.rn.bf16.f32 y, %4;\n\t"
        "mov.b32 %0, {x, y};\n\t"
        "cvt.f32.bf16 r0, x;\n\t"
        "cvt.f32.bf16 r1, y;\n\t"
        "sub.f32 %1, %3, r0;\n\t"
        "sub.f32 %2, %4, r1; }"
        : "=r"(hp), "=f"(l0), "=f"(l1) : "f"(h0), "f"(h1));
    return hp;
}
__device__ __forceinline__ uint32_t pack_bf16x2(float x0, float x1) {
    uint32_t r;
    asm("{ .reg .b16 x, y; cvt.rn.bf16.f32 x, %1; cvt.rn.bf16.f32 y, %2; mov.b32 %0, {x, y}; }"
        : "=r"(r) : "f"(x0), "f"(x1));
    return r;
}

// ---------------- prepared weights ----------------
struct SmallV {
    float ws[HD];       // layer1 weight on carry (0 for v=0)
    float we[HD];       // layer1 weight on noise
    float b1[HD];
    float2 b2w3[HD];    // {B2[j], W3[j]}
    float b3;
    float std_;
    float pad[2];
};                       // 1296 B
__device__ __align__(16) SmallV g_small[NV];
// W2^T (rows j = output, cols k = input) as swizzled bf16 smem image, hi/lo splits.
// element (j,k): idx = j*64 + ((k/8 ^ (j&7))*8) + (k%8)
__device__ __align__(16) __nv_bfloat16 g_W2T[NV][2][HD * HD];

__global__ void prep_kernel(
    const float* __restrict__ stds,
    const float* __restrict__ w0_1, const float* __restrict__ b0_1,
    const float* __restrict__ w0_2, const float* __restrict__ b0_2,
    const float* __restrict__ w0_3, const float* __restrict__ b0_3,
    const float* __restrict__ W1,   const float* __restrict__ B1,
    const float* __restrict__ W2,   const float* __restrict__ B2,
    const float* __restrict__ W3,   const float* __restrict__ B3)
{
    const int v = blockIdx.x;
    const int tid = threadIdx.x;
    const float* w2 = (v == 0) ? w0_2 : W2 + (size_t)(v - 1) * HD * HD;  // [k][j]

    for (int t = tid; t < HD * HD; t += blockDim.x) {
        int k = t / HD, j = t % HD;
        float x = w2[k * HD + j];
        __nv_bfloat16 hb = __float2bfloat16_rn(x);
        float lo = x - __bfloat162float(hb);
        __nv_bfloat16 lb = __float2bfloat16_rn(lo);
        int idx = j * HD + (((k >> 3) ^ (j & 7)) << 3) + (k & 7);
        g_W2T[v][0][idx] = hb;
        g_W2T[v][1][idx] = lb;
    }
    if (tid < HD) {
        SmallV* sv = &g_small[v];
        if (v == 0) {
            sv->ws[tid] = 0.0f;
            sv->we[tid] = w0_1[tid];
            sv->b1[tid] = b0_1[tid];
            sv->b2w3[tid] = make_float2(b0_2[tid], w0_3[tid]);
            if (tid == 0) { sv->b3 = b0_3[0]; sv->std_ = fabsf(stds[0]); }
        } else {
            int i = v - 1;
            sv->ws[tid] = W1[(size_t)i * 2 * HD + tid];
            sv->we[tid] = W1[(size_t)i * 2 * HD + HD + tid];
            sv->b1[tid] = B1[(size_t)i * HD + tid];
            sv->b2w3[tid] = make_float2(B2[(size_t)i * HD + tid], W3[(size_t)i * HD + tid]);
            if (tid == 0) { sv->b3 = B3[i]; sv->std_ = fabsf(stds[v]); }
        }
    }
}

// ---------------- main kernel ----------------
__global__ __launch_bounds__(TPB, 2)
void ncm_hmma_kernel(const float* __restrict__ noise, float* __restrict__ out, int nsamp)
{
    __shared__ __align__(16) __nv_bfloat16 sW[2][HD * HD];  // 16 KB  W2^T hi/lo
    __shared__ __align__(16) __nv_bfloat16 sA[TPB * HD];    // 16 KB  activations (reused hi->lo)
    __shared__ __align__(16) SmallV sV;
    __shared__ float sCar[TPB];

    const int tid  = threadIdx.x;
    const int w    = tid >> 5;
    const int lane = tid & 31;
    const int l7   = lane & 7;   // row-within-8 for ldmatrix addressing
    const int l3   = lane & 3;
    const int mi   = lane >> 3;  // ldmatrix matrix index 0..3

    const uint32_t sA_b  = smem_u32(sA);
    const uint32_t sWh_b = smem_u32(&sW[0][0]);
    const uint32_t sWl_b = smem_u32(&sW[1][0]);

    // A ldmatrix row for this lane (before mt offset): rows are warp-local samples
    const int arow = w * 32 + (mi & 1) * 8 + l7;      // row & 7 == l7
    const uint32_t a_rowoff = sA_b + (uint32_t)arow * 128u;

    const long long n = (long long)blockIdx.x * TPB + tid;
    const bool active = n < (long long)nsamp;
    float carry = 0.0f;

    for (int v = 0; v < NV; v++) {
        __syncthreads();  // all warps done with sW/sV of previous v

        // ---- stage W2^T hi/lo (16 KB) + small params ----
        {
            const uint4* src = (const uint4*)&g_W2T[v][0][0];
            uint4* dst = (uint4*)&sW[0][0];
            #pragma unroll
            for (int c = 0; c < 8; c++)
                dst[tid + c * TPB] = src[tid + c * TPB];
            const float* s2 = (const float*)&g_small[v];
            float* d2 = (float*)&sV;
            #pragma unroll
            for (int c = 0; c < 3; c++) {
                int k = tid + c * TPB;
                if (k < (int)(sizeof(SmallV) / 4)) d2[k] = s2[k];
            }
        }
        __syncthreads();

        // ---- layer 1 (fp32) + bf16 split ----
        const float e = active ? noise[(long long)v * nsamp + n] * sV.std_ : 0.0f;
        uint32_t phi[32], plo[32];
        #pragma unroll
        for (int c = 0; c < 32; c++) {
            float h0 = fmaxf(fmaf(carry, sV.ws[2 * c],     fmaf(e, sV.we[2 * c],     sV.b1[2 * c])),     0.0f);
            float h1 = fmaxf(fmaf(carry, sV.ws[2 * c + 1], fmaf(e, sV.we[2 * c + 1], sV.b1[2 * c + 1])), 0.0f);
            float l0, l1;
            phi[c] = split_hi_pair(h0, h1, l0, l1);
            plo[c] = pack_bf16x2(l0, l1);
        }

        // ---- stage A-hi (swizzled, warp-local rows), load fragments ----
        uint4* aq = (uint4*)sA;
        #pragma unroll
        for (int c8 = 0; c8 < 8; c8++) {
            int swz = c8 ^ (tid & 7);
            aq[tid * 8 + swz] = make_uint4(phi[4 * c8], phi[4 * c8 + 1], phi[4 * c8 + 2], phi[4 * c8 + 3]);
        }
        __syncwarp();
        uint32_t ah[2][4][4];
        #pragma unroll
        for (int mt = 0; mt < 2; mt++)
            #pragma unroll
            for (int kt = 0; kt < 4; kt++) {
                int c8 = kt * 2 + (mi >> 1);
                uint32_t addr = a_rowoff + (uint32_t)(mt * 16 * 128) + (uint32_t)((c8 ^ l7) * 16);
                ldmx4(ah[mt][kt][0], ah[mt][kt][1], ah[mt][kt][2], ah[mt][kt][3], addr);
            }
        __syncwarp();
        // ---- stage A-lo into the same buffer, load fragments ----
        #pragma unroll
        for (int c8 = 0; c8 < 8; c8++) {
            int swz = c8 ^ (tid & 7);
            aq[tid * 8 + swz] = make_uint4(plo[4 * c8], plo[4 * c8 + 1], plo[4 * c8 + 2], plo[4 * c8 + 3]);
        }
        __syncwarp();
        uint32_t al[2][4][4];
        #pragma unroll
        for (int mt = 0; mt < 2; mt++)
            #pragma unroll
            for (int kt = 0; kt < 4; kt++) {
                int c8 = kt * 2 + (mi >> 1);
                uint32_t addr = a_rowoff + (uint32_t)(mt * 16 * 128) + (uint32_t)((c8 ^ l7) * 16);
                ldmx4(al[mt][kt][0], al[mt][kt][1], al[mt][kt][2], al[mt][kt][3], addr);
            }
        __syncwarp();

        // ---- GEMM: acc = Ahi*Bhi + Ahi*Blo + Alo*Bhi ----
        float acc[2][8][4];
        #pragma unroll
        for (int mt = 0; mt < 2; mt++)
            #pragma unroll
            for (int jt = 0; jt < 8; jt++)
                #pragma unroll
                for (int q = 0; q < 4; q++) acc[mt][jt][q] = 0.0f;

        #pragma unroll
        for (int jt = 0; jt < 8; jt++) {
            // B rows are n = jt*8 + l7; chunks c8 = (base + mi) ^ (n&7), n&7 == l7
            uint32_t nrowoff = (uint32_t)((jt * 8 + l7) * 128);
            uint32_t bh[8], bl[8];
            {
                uint32_t a0 = sWh_b + nrowoff + (uint32_t)(((0 + mi) ^ l7) * 16);
                uint32_t a1 = sWh_b + nrowoff + (uint32_t)(((4 + mi) ^ l7) * 16);
                ldmx4(bh[0], bh[1], bh[2], bh[3], a0);
                ldmx4(bh[4], bh[5], bh[6], bh[7], a1);
                uint32_t a2 = sWl_b + nrowoff + (uint32_t)(((0 + mi) ^ l7) * 16);
                uint32_t a3 = sWl_b + nrowoff + (uint32_t)(((4 + mi) ^ l7) * 16);
                ldmx4(bl[0], bl[1], bl[2], bl[3], a2);
                ldmx4(bl[4], bl[5], bl[6], bl[7], a3);
            }
            #pragma unroll
            for (int mt = 0; mt < 2; mt++) {
                #pragma unroll
                for (int kt = 0; kt < 4; kt++) {
                    mma_bf16(acc[mt][jt][0], acc[mt][jt][1], acc[mt][jt][2], acc[mt][jt][3],
                             ah[mt][kt][0], ah[mt][kt][1], ah[mt][kt][2], ah[mt][kt][3],
                             bh[2 * kt], bh[2 * kt + 1]);
                    mma_bf16(acc[mt][jt][0], acc[mt][jt][1], acc[mt][jt][2], acc[mt][jt][3],
                             ah[mt][kt][0], ah[mt][kt][1], ah[mt][kt][2], ah[mt][kt][3],
                             bl[2 * kt], bl[2 * kt + 1]);
                    mma_bf16(acc[mt][jt][0], acc[mt][jt][1], acc[mt][jt][2], acc[mt][jt][3],
                             al[mt][kt][0], al[mt][kt][1], al[mt][kt][2], al[mt][kt][3],
                             bh[2 * kt], bh[2 * kt + 1]);
                }
            }
        }

        // ---- epilogue: relu(D + B2) dot W3, reduce across group-of-4 lanes ----
        float p[2][2] = {{0, 0}, {0, 0}};   // [mt][row r / row r+8]
        #pragma unroll
        for (int jt = 0; jt < 8; jt++) {
            int j0 = jt * 8 + 2 * l3;
            float2 bw0 = sV.b2w3[j0];
            float2 bw1 = sV.b2w3[j0 + 1];
            #pragma unroll
            for (int mt = 0; mt < 2; mt++) {
                p[mt][0] = fmaf(fmaxf(acc[mt][jt][0] + bw0.x, 0.0f), bw0.y, p[mt][0]);
                p[mt][0] = fmaf(fmaxf(acc[mt][jt][1] + bw1.x, 0.0f), bw1.y, p[mt][0]);
                p[mt][1] = fmaf(fmaxf(acc[mt][jt][2] + bw0.x, 0.0f), bw0.y, p[mt][1]);
                p[mt][1] = fmaf(fmaxf(acc[mt][jt][3] + bw1.x, 0.0f), bw1.y, p[mt][1]);
            }
        }
        #pragma unroll
        for (int mt = 0; mt < 2; mt++)
            #pragma unroll
            for (int q = 0; q < 2; q++) {
                p[mt][q] += __shfl_xor_sync(0xffffffffu, p[mt][q], 1);
                p[mt][q] += __shfl_xor_sync(0xffffffffu, p[mt][q], 2);
            }
        if (l3 == 0) {
            int r = lane >> 2;                 // 0..7
            sCar[w * 32 + r]      = p[0][0];
            sCar[w * 32 + r + 8]  = p[0][1];
            sCar[w * 32 + r + 16] = p[1][0];
            sCar[w * 32 + r + 24] = p[1][1];
        }
        __syncwarp();
        carry = sCar[w * 32 + lane] + sV.b3;

        if (active) out[(long long)v * nsamp + n] = carry;
    }
}

extern "C" void kernel_launch(void* const* d_in, const int* in_sizes, int n_in,
                              void* d_out, int out_size) {
    const float* noise = (const float*)d_in[0];
    const float* stds  = (const float*)d_in[1];
    const float* w0_1  = (const float*)d_in[2];
    const float* b0_1  = (const float*)d_in[3];
    const float* w0_2  = (const float*)d_in[4];
    const float* b0_2  = (const float*)d_in[5];
    const float* w0_3  = (const float*)d_in[6];
    const float* b0_3  = (const float*)d_in[7];
    const float* W1    = (const float*)d_in[8];
    const float* B1    = (const float*)d_in[9];
    const float* W2    = (const float*)d_in[10];
    const float* B2    = (const float*)d_in[11];
    const float* W3    = (const float*)d_in[12];
    const float* B3    = (const float*)d_in[13];

    const int nsamp = in_sizes[0] / NV;
    prep_kernel<<<NV, 256>>>(stds, w0_1, b0_1, w0_2, b0_2, w0_3, b0_3,
                             W1, B1, W2, B2, W3, B3);
    const int grid = (nsamp + TPB - 1) / TPB;
    ncm_hmma_kernel<<<grid, TPB>>>(noise, (float*)d_out, nsamp);
}

// round 5
// speedup vs baseline: 3.1424x; 1.1129x over previous
#include <cuda_runtime.h>
#include <cuda_bf16.h>
#include <cstdint>

#define HD   64
#define NV   16
#define TPB  128   // threads per CTA = samples per CTA (M)

// ---------------- helpers ----------------
__device__ __forceinline__ uint32_t smem_u32(const void* p) {
    uint32_t a;
    asm("{ .reg .u64 t; cvta.to.shared.u64 t, %1; cvt.u32.u64 %0, t; }" : "=r"(a) : "l"(p));
    return a;
}
__device__ __forceinline__ void ldmx4(uint32_t& r0, uint32_t& r1, uint32_t& r2, uint32_t& r3,
                                      uint32_t addr) {
    asm volatile("ldmatrix.sync.aligned.m8n8.x4.shared.b16 {%0,%1,%2,%3}, [%4];"
                 : "=r"(r0), "=r"(r1), "=r"(r2), "=r"(r3) : "r"(addr));
}
__device__ __forceinline__ void mma_bf16(float* c,
                                         const uint32_t* a,
                                         uint32_t b0, uint32_t b1) {
    asm volatile("mma.sync.aligned.m16n8k16.row.col.f32.bf16.bf16.f32 "
                 "{%0,%1,%2,%3}, {%4,%5,%6,%7}, {%8,%9}, {%0,%1,%2,%3};"
                 : "+f"(c[0]), "+f"(c[1]), "+f"(c[2]), "+f"(c[3])
                 : "r"(a[0]), "r"(a[1]), "r"(a[2]), "r"(a[3]), "r"(b0), "r"(b1));
}
__device__ __forceinline__ uint32_t split_hi_pair(float h0, float h1, float& l0, float& l1) {
    uint32_t hp;
    asm("{ .reg .b16 x, y; .reg .f32 r0, r1;\n\t"
        "cvt.rn.bf16.f32 x, %3;\n\t"
        "cvt.rn.bf16.f32 y, %4;\n\t"
        "mov.b32 %0, {x, y};\n\t"
        "cvt.f32.bf16 r0, x;\n\t"
        "cvt.f32.bf16 r1, y;\n\t"
        "sub.f32 %1, %3, r0;\n\t"
        "sub.f32 %2, %4, r1; }"
        : "=r"(hp), "=f"(l0), "=f"(l1) : "f"(h0), "f"(h1));
    return hp;
}
__device__ __forceinline__ uint32_t pack_bf16x2(float x0, float x1) {
    uint32_t r;
    asm("{ .reg .b16 x, y; cvt.rn.bf16.f32 x, %1; cvt.rn.bf16.f32 y, %2; mov.b32 %0, {x, y}; }"
        : "=r"(r) : "f"(x0), "f"(x1));
    return r;
}

// ---------------- prepared weights ----------------
struct SmallV {
    float4 l1w[32];     // {ws[2c], ws[2c+1], we[2c], we[2c+1]}
    float2 l1b[32];     // {b1[2c], b1[2c+1]}
    float2 b2w3[HD];    // {B2[j], W3[j]}
    float b3;
    float std_;
    float pad[2];
};                       // 1312 B
__device__ __align__(16) SmallV g_small[NV];
// W2^T (rows j = output, cols k = input) as swizzled bf16 smem image, hi/lo splits.
// element (j,k): idx = j*64 + ((k/8 ^ (j&7))*8) + (k%8)
__device__ __align__(16) __nv_bfloat16 g_W2T[NV][2][HD * HD];

__global__ void prep_kernel(
    const float* __restrict__ stds,
    const float* __restrict__ w0_1, const float* __restrict__ b0_1,
    const float* __restrict__ w0_2, const float* __restrict__ b0_2,
    const float* __restrict__ w0_3, const float* __restrict__ b0_3,
    const float* __restrict__ W1,   const float* __restrict__ B1,
    const float* __restrict__ W2,   const float* __restrict__ B2,
    const float* __restrict__ W3,   const float* __restrict__ B3)
{
    const int v = blockIdx.x;
    const int tid = threadIdx.x;
    const float* w2 = (v == 0) ? w0_2 : W2 + (size_t)(v - 1) * HD * HD;  // [k][j]

    for (int t = tid; t < HD * HD; t += blockDim.x) {
        int k = t / HD, j = t % HD;
        float x = w2[k * HD + j];
        __nv_bfloat16 hb = __float2bfloat16_rn(x);
        float lo = x - __bfloat162float(hb);
        __nv_bfloat16 lb = __float2bfloat16_rn(lo);
        int idx = j * HD + (((k >> 3) ^ (j & 7)) << 3) + (k & 7);
        g_W2T[v][0][idx] = hb;
        g_W2T[v][1][idx] = lb;
    }
    SmallV* sv = &g_small[v];
    if (tid < 32) {
        int c = tid;
        float ws0, ws1, we0, we1, b10, b11;
        if (v == 0) {
            ws0 = ws1 = 0.0f;
            we0 = w0_1[2 * c]; we1 = w0_1[2 * c + 1];
            b10 = b0_1[2 * c]; b11 = b0_1[2 * c + 1];
        } else {
            int i = v - 1;
            ws0 = W1[(size_t)i * 2 * HD + 2 * c];
            ws1 = W1[(size_t)i * 2 * HD + 2 * c + 1];
            we0 = W1[(size_t)i * 2 * HD + HD + 2 * c];
            we1 = W1[(size_t)i * 2 * HD + HD + 2 * c + 1];
            b10 = B1[(size_t)i * HD + 2 * c];
            b11 = B1[(size_t)i * HD + 2 * c + 1];
        }
        sv->l1w[c] = make_float4(ws0, ws1, we0, we1);
        sv->l1b[c] = make_float2(b10, b11);
    }
    if (tid < HD) {
        if (v == 0) {
            sv->b2w3[tid] = make_float2(b0_2[tid], w0_3[tid]);
            if (tid == 0) { sv->b3 = b0_3[0]; sv->std_ = fabsf(stds[0]); }
        } else {
            int i = v - 1;
            sv->b2w3[tid] = make_float2(B2[(size_t)i * HD + tid], W3[(size_t)i * HD + tid]);
            if (tid == 0) { sv->b3 = B3[i]; sv->std_ = fabsf(stds[v]); }
        }
    }
}

// ---------------- main kernel ----------------
__global__ __launch_bounds__(TPB, 3)
void ncm_hmma_kernel(const float* __restrict__ noise, float* __restrict__ out, int nsamp)
{
    __shared__ __align__(16) __nv_bfloat16 sW[2][HD * HD];  // 16 KB  W2^T hi/lo
    __shared__ __align__(16) __nv_bfloat16 sA[TPB * HD];    // 16 KB  activations (reused hi->lo)
    __shared__ __align__(16) SmallV sV;
    __shared__ float sCar[TPB];

    const int tid  = threadIdx.x;
    const int w    = tid >> 5;
    const int lane = tid & 31;
    const int l7   = lane & 7;
    const int l3   = lane & 3;
    const int mi   = lane >> 3;  // ldmatrix matrix index 0..3

    const uint32_t sA_b  = smem_u32(sA);
    const uint32_t sWh_b = smem_u32(&sW[0][0]);
    const uint32_t sWl_b = smem_u32(&sW[1][0]);

    const int arow = w * 32 + (mi & 1) * 8 + l7;      // row & 7 == l7
    const uint32_t a_rowoff = sA_b + (uint32_t)arow * 128u;

    const long long n = (long long)blockIdx.x * TPB + tid;
    const bool active = n < (long long)nsamp;
    float carry = 0.0f;

    for (int v = 0; v < NV; v++) {
        __syncthreads();  // all warps done with sW/sV of previous v

        // ---- stage W2^T hi/lo (16 KB) + small params ----
        {
            const uint4* src = (const uint4*)&g_W2T[v][0][0];
            uint4* dst = (uint4*)&sW[0][0];
            #pragma unroll
            for (int c = 0; c < 8; c++)
                dst[tid + c * TPB] = src[tid + c * TPB];
            const float* s2 = (const float*)&g_small[v];
            float* d2 = (float*)&sV;
            #pragma unroll
            for (int c = 0; c < 3; c++) {
                int k = tid + c * TPB;
                if (k < (int)(sizeof(SmallV) / 4)) d2[k] = s2[k];
            }
        }
        __syncthreads();

        // ---- layer 1 (fp32) + bf16 split ----
        const float e = active ? noise[(long long)v * nsamp + n] * sV.std_ : 0.0f;
        uint32_t phi[32], plo[32];
        #pragma unroll
        for (int c = 0; c < 32; c++) {
            float4 wv = sV.l1w[c];
            float2 bv = sV.l1b[c];
            float h0 = fmaxf(fmaf(carry, wv.x, fmaf(e, wv.z, bv.x)), 0.0f);
            float h1 = fmaxf(fmaf(carry, wv.y, fmaf(e, wv.w, bv.y)), 0.0f);
            float l0, l1;
            phi[c] = split_hi_pair(h0, h1, l0, l1);
            plo[c] = pack_bf16x2(l0, l1);
        }

        // ---- stage A-hi (swizzled, warp-local rows), load fragments ----
        uint4* aq = (uint4*)sA;
        #pragma unroll
        for (int c8 = 0; c8 < 8; c8++) {
            int swz = c8 ^ (tid & 7);
            aq[tid * 8 + swz] = make_uint4(phi[4 * c8], phi[4 * c8 + 1], phi[4 * c8 + 2], phi[4 * c8 + 3]);
        }
        __syncwarp();
        uint32_t ah[2][4][4];
        #pragma unroll
        for (int mt = 0; mt < 2; mt++)
            #pragma unroll
            for (int kt = 0; kt < 4; kt++) {
                int c8 = kt * 2 + (mi >> 1);
                uint32_t addr = a_rowoff + (uint32_t)(mt * 16 * 128) + (uint32_t)((c8 ^ l7) * 16);
                ldmx4(ah[mt][kt][0], ah[mt][kt][1], ah[mt][kt][2], ah[mt][kt][3], addr);
            }
        __syncwarp();
        // ---- stage A-lo into the same buffer, load fragments ----
        #pragma unroll
        for (int c8 = 0; c8 < 8; c8++) {
            int swz = c8 ^ (tid & 7);
            aq[tid * 8 + swz] = make_uint4(plo[4 * c8], plo[4 * c8 + 1], plo[4 * c8 + 2], plo[4 * c8 + 3]);
        }
        __syncwarp();
        uint32_t al[2][4][4];
        #pragma unroll
        for (int mt = 0; mt < 2; mt++)
            #pragma unroll
            for (int kt = 0; kt < 4; kt++) {
                int c8 = kt * 2 + (mi >> 1);
                uint32_t addr = a_rowoff + (uint32_t)(mt * 16 * 128) + (uint32_t)((c8 ^ l7) * 16);
                ldmx4(al[mt][kt][0], al[mt][kt][1], al[mt][kt][2], al[mt][kt][3], addr);
            }
        __syncwarp();

        // ---- GEMM in jt-pairs: 4 independent acc chains, kt outer ----
        float p[2][2] = {{0, 0}, {0, 0}};   // [mt][row r / row r+8] epilogue partials

        #pragma unroll
        for (int jtp = 0; jtp < 4; jtp++) {
            // load B fragments for jt = 2*jtp and 2*jtp+1
            uint32_t bh[2][8], bl[2][8];
            #pragma unroll
            for (int jt2 = 0; jt2 < 2; jt2++) {
                int jt = 2 * jtp + jt2;
                uint32_t nrowoff = (uint32_t)((jt * 8 + l7) * 128);
                uint32_t a0 = sWh_b + nrowoff + (uint32_t)(((0 + mi) ^ l7) * 16);
                uint32_t a1 = sWh_b + nrowoff + (uint32_t)(((4 + mi) ^ l7) * 16);
                ldmx4(bh[jt2][0], bh[jt2][1], bh[jt2][2], bh[jt2][3], a0);
                ldmx4(bh[jt2][4], bh[jt2][5], bh[jt2][6], bh[jt2][7], a1);
                uint32_t a2 = sWl_b + nrowoff + (uint32_t)(((0 + mi) ^ l7) * 16);
                uint32_t a3 = sWl_b + nrowoff + (uint32_t)(((4 + mi) ^ l7) * 16);
                ldmx4(bl[jt2][0], bl[jt2][1], bl[jt2][2], bl[jt2][3], a2);
                ldmx4(bl[jt2][4], bl[jt2][5], bl[jt2][6], bl[jt2][7], a3);
            }

            float acc[2][2][4];   // [jt2][mt][quad]
            #pragma unroll
            for (int jt2 = 0; jt2 < 2; jt2++)
                #pragma unroll
                for (int mt = 0; mt < 2; mt++)
                    #pragma unroll
                    for (int q = 0; q < 4; q++) acc[jt2][mt][q] = 0.0f;

            // kt outer; issue order round-robins the 4 (jt2,mt) accumulators
            #pragma unroll
            for (int kt = 0; kt < 4; kt++) {
                #pragma unroll
                for (int jt2 = 0; jt2 < 2; jt2++)
                    #pragma unroll
                    for (int mt = 0; mt < 2; mt++)
                        mma_bf16(acc[jt2][mt], ah[mt][kt], bh[jt2][2 * kt], bh[jt2][2 * kt + 1]);
                #pragma unroll
                for (int jt2 = 0; jt2 < 2; jt2++)
                    #pragma unroll
                    for (int mt = 0; mt < 2; mt++)
                        mma_bf16(acc[jt2][mt], ah[mt][kt], bl[jt2][2 * kt], bl[jt2][2 * kt + 1]);
                #pragma unroll
                for (int jt2 = 0; jt2 < 2; jt2++)
                    #pragma unroll
                    for (int mt = 0; mt < 2; mt++)
                        mma_bf16(acc[jt2][mt], al[mt][kt], bh[jt2][2 * kt], bh[jt2][2 * kt + 1]);
            }

            // fold this jt-pair into epilogue partials
            #pragma unroll
            for (int jt2 = 0; jt2 < 2; jt2++) {
                int j0 = (2 * jtp + jt2) * 8 + 2 * l3;
                float2 bw0 = sV.b2w3[j0];
                float2 bw1 = sV.b2w3[j0 + 1];
                #pragma unroll
                for (int mt = 0; mt < 2; mt++) {
                    p[mt][0] = fmaf(fmaxf(acc[jt2][mt][0] + bw0.x, 0.0f), bw0.y, p[mt][0]);
                    p[mt][0] = fmaf(fmaxf(acc[jt2][mt][1] + bw1.x, 0.0f), bw1.y, p[mt][0]);
                    p[mt][1] = fmaf(fmaxf(acc[jt2][mt][2] + bw0.x, 0.0f), bw0.y, p[mt][1]);
                    p[mt][1] = fmaf(fmaxf(acc[jt2][mt][3] + bw1.x, 0.0f), bw1.y, p[mt][1]);
                }
            }
        }

        // ---- reduce across group-of-4 lanes, scatter carry back ----
        #pragma unroll
        for (int mt = 0; mt < 2; mt++)
            #pragma unroll
            for (int q = 0; q < 2; q++) {
                p[mt][q] += __shfl_xor_sync(0xffffffffu, p[mt][q], 1);
                p[mt][q] += __shfl_xor_sync(0xffffffffu, p[mt][q], 2);
            }
        if (l3 == 0) {
            int r = lane >> 2;                 // 0..7
            sCar[w * 32 + r]      = p[0][0];
            sCar[w * 32 + r + 8]  = p[0][1];
            sCar[w * 32 + r + 16] = p[1][0];
            sCar[w * 32 + r + 24] = p[1][1];
        }
        __syncwarp();
        carry = sCar[w * 32 + lane] + sV.b3;

        if (active) out[(long long)v * nsamp + n] = carry;
    }
}

extern "C" void kernel_launch(void* const* d_in, const int* in_sizes, int n_in,
                              void* d_out, int out_size) {
    const float* noise = (const float*)d_in[0];
    const float* stds  = (const float*)d_in[1];
    const float* w0_1  = (const float*)d_in[2];
    const float* b0_1  = (const float*)d_in[3];
    const float* w0_2  = (const float*)d_in[4];
    const float* b0_2  = (const float*)d_in[5];
    const float* w0_3  = (const float*)d_in[6];
    const float* b0_3  = (const float*)d_in[7];
    const float* W1    = (const float*)d_in[8];
    const float* B1    = (const float*)d_in[9];
    const float* W2    = (const float*)d_in[10];
    const float* B2    = (const float*)d_in[11];
    const float* W3    = (const float*)d_in[12];
    const float* B3    = (const float*)d_in[13];

    const int nsamp = in_sizes[0] / NV;
    prep_kernel<<<NV, 256>>>(stds, w0_1, b0_1, w0_2, b0_2, w0_3, b0_3,
                             W1, B1, W2, B2, W3, B3);
    const int grid = (nsamp + TPB - 1) / TPB;
    ncm_hmma_kernel<<<grid, TPB>>>(noise, (float*)d_out, nsamp);
}

// round 6
// speedup vs baseline: 3.4770x; 1.1065x over previous
#include <cuda_runtime.h>
#include <cuda_bf16.h>
#include <cstdint>

#define HD   64
#define NV   16
#define TPB  128   // threads per CTA = samples per CTA (M)

// ---------------- helpers ----------------
__device__ __forceinline__ uint32_t smem_u32(const void* p) {
    uint32_t a;
    asm("{ .reg .u64 t; cvta.to.shared.u64 t, %1; cvt.u32.u64 %0, t; }" : "=r"(a) : "l"(p));
    return a;
}
__device__ __forceinline__ void ldmx4(uint32_t& r0, uint32_t& r1, uint32_t& r2, uint32_t& r3,
                                      uint32_t addr) {
    asm volatile("ldmatrix.sync.aligned.m8n8.x4.shared.b16 {%0,%1,%2,%3}, [%4];"
                 : "=r"(r0), "=r"(r1), "=r"(r2), "=r"(r3) : "r"(addr));
}
__device__ __forceinline__ void mma_bf16(float* c, const uint32_t* a,
                                         uint32_t b0, uint32_t b1) {
    asm volatile("mma.sync.aligned.m16n8k16.row.col.f32.bf16.bf16.f32 "
                 "{%0,%1,%2,%3}, {%4,%5,%6,%7}, {%8,%9}, {%0,%1,%2,%3};"
                 : "+f"(c[0]), "+f"(c[1]), "+f"(c[2]), "+f"(c[3])
                 : "r"(a[0]), "r"(a[1]), "r"(a[2]), "r"(a[3]), "r"(b0), "r"(b1));
}
__device__ __forceinline__ uint32_t split_hi_pair(float h0, float h1, float& l0, float& l1) {
    uint32_t hp;
    asm("{ .reg .b16 x, y; .reg .f32 r0, r1;\n\t"
        "cvt.rn.bf16.f32 x, %3;\n\t"
        "cvt.rn.bf16.f32 y, %4;\n\t"
        "mov.b32 %0, {x, y};\n\t"
        "cvt.f32.bf16 r0, x;\n\t"
        "cvt.f32.bf16 r1, y;\n\t"
        "sub.f32 %1, %3, r0;\n\t"
        "sub.f32 %2, %4, r1; }"
        : "=r"(hp), "=f"(l0), "=f"(l1) : "f"(h0), "f"(h1));
    return hp;
}
__device__ __forceinline__ uint32_t pack_bf16x2(float x0, float x1) {
    uint32_t r;
    asm("{ .reg .b16 x, y; cvt.rn.bf16.f32 x, %1; cvt.rn.bf16.f32 y, %2; mov.b32 %0, {x, y}; }"
        : "=r"(r) : "f"(x0), "f"(x1));
    return r;
}
__device__ __forceinline__ void cp_async16(uint32_t smem_dst, const void* gmem_src) {
    asm volatile("cp.async.cg.shared.global [%0], [%1], 16;"
                 :: "r"(smem_dst), "l"(gmem_src) : "memory");
}

// ---------------- prepared weights ----------------
struct SmallV {
    float4 l1w[32];     // {ws[2c], ws[2c+1], we[2c], we[2c+1]}
    float2 l1b[32];     // {b1[2c], b1[2c+1]}
    float2 b2w3[HD];    // {B2[j], W3[j]}
    float b3;
    float std_;
    float pad[6];
};                       // 1312 B = 82 * 16
__device__ __align__(16) SmallV g_small[NV];
// W2^T (rows j = output, cols k = input) as swizzled bf16 smem image, hi/lo splits.
// element (j,k): idx = j*64 + ((k/8 ^ (j&7))*8) + (k%8)
__device__ __align__(16) __nv_bfloat16 g_W2T[NV][2][HD * HD];

__global__ void prep_kernel(
    const float* __restrict__ stds,
    const float* __restrict__ w0_1, const float* __restrict__ b0_1,
    const float* __restrict__ w0_2, const float* __restrict__ b0_2,
    const float* __restrict__ w0_3, const float* __restrict__ b0_3,
    const float* __restrict__ W1,   const float* __restrict__ B1,
    const float* __restrict__ W2,   const float* __restrict__ B2,
    const float* __restrict__ W3,   const float* __restrict__ B3)
{
    const int v = blockIdx.x;
    const int tid = threadIdx.x;
    const float* w2 = (v == 0) ? w0_2 : W2 + (size_t)(v - 1) * HD * HD;  // [k][j]

    for (int t = tid; t < HD * HD; t += blockDim.x) {
        int k = t / HD, j = t % HD;
        float x = w2[k * HD + j];
        __nv_bfloat16 hb = __float2bfloat16_rn(x);
        float lo = x - __bfloat162float(hb);
        __nv_bfloat16 lb = __float2bfloat16_rn(lo);
        int idx = j * HD + (((k >> 3) ^ (j & 7)) << 3) + (k & 7);
        g_W2T[v][0][idx] = hb;
        g_W2T[v][1][idx] = lb;
    }
    SmallV* sv = &g_small[v];
    if (tid < 32) {
        int c = tid;
        float ws0, ws1, we0, we1, b10, b11;
        if (v == 0) {
            ws0 = ws1 = 0.0f;
            we0 = w0_1[2 * c]; we1 = w0_1[2 * c + 1];
            b10 = b0_1[2 * c]; b11 = b0_1[2 * c + 1];
        } else {
            int i = v - 1;
            ws0 = W1[(size_t)i * 2 * HD + 2 * c];
            ws1 = W1[(size_t)i * 2 * HD + 2 * c + 1];
            we0 = W1[(size_t)i * 2 * HD + HD + 2 * c];
            we1 = W1[(size_t)i * 2 * HD + HD + 2 * c + 1];
            b10 = B1[(size_t)i * HD + 2 * c];
            b11 = B1[(size_t)i * HD + 2 * c + 1];
        }
        sv->l1w[c] = make_float4(ws0, ws1, we0, we1);
        sv->l1b[c] = make_float2(b10, b11);
    }
    if (tid < HD) {
        if (v == 0) {
            sv->b2w3[tid] = make_float2(b0_2[tid], w0_3[tid]);
            if (tid == 0) { sv->b3 = b0_3[0]; sv->std_ = fabsf(stds[0]); }
        } else {
            int i = v - 1;
            sv->b2w3[tid] = make_float2(B2[(size_t)i * HD + tid], W3[(size_t)i * HD + tid]);
            if (tid == 0) { sv->b3 = B3[i]; sv->std_ = fabsf(stds[v]); }
        }
    }
}

// ---------------- main kernel ----------------
struct __align__(128) Stage {
    __nv_bfloat16 w[2][HD * HD];   // 16 KB, W2^T hi/lo (swizzled)
    SmallV sv;                     // 1312 B
};

__global__ __launch_bounds__(TPB, 3)
void ncm_hmma_kernel(const float* __restrict__ noise, float* __restrict__ out, int nsamp)
{
    __shared__ Stage sStg[2];
    __shared__ float sCar[TPB];

    const int tid  = threadIdx.x;
    const int w    = tid >> 5;
    const int lane = tid & 31;
    const int l7   = lane & 7;
    const int l3   = lane & 3;
    const int g    = lane >> 2;  // group id 0..7 (fragment row base)
    const int mi   = lane >> 3;  // ldmatrix matrix index 0..3

    const long long n = (long long)blockIdx.x * TPB + tid;
    const bool active = n < (long long)nsamp;
    float carry = 0.0f;

    // prologue: prefetch stage 0
    {
        const uint4* srcw = (const uint4*)&g_W2T[0][0][0];
        uint4* dstw = (uint4*)&sStg[0].w[0][0];
        #pragma unroll
        for (int c = 0; c < 8; c++)
            cp_async16(smem_u32(dstw + tid + c * TPB), srcw + tid + c * TPB);
        if (tid < 82)
            cp_async16(smem_u32(((uint4*)&sStg[0].sv) + tid), ((const uint4*)&g_small[0]) + tid);
        asm volatile("cp.async.commit_group;" ::: "memory");
    }

    for (int v = 0; v < NV; v++) {
        Stage* st = &sStg[v & 1];

        // prefetch v+1 into the other buffer (consumers finished last iter, barrier below)
        if (v + 1 < NV) {
            Stage* nx = &sStg[(v + 1) & 1];
            const uint4* srcw = (const uint4*)&g_W2T[v + 1][0][0];
            uint4* dstw = (uint4*)&nx->w[0][0];
            #pragma unroll
            for (int c = 0; c < 8; c++)
                cp_async16(smem_u32(dstw + tid + c * TPB), srcw + tid + c * TPB);
            if (tid < 82)
                cp_async16(smem_u32(((uint4*)&nx->sv) + tid), ((const uint4*)&g_small[v + 1]) + tid);
            asm volatile("cp.async.commit_group;" ::: "memory");
            asm volatile("cp.async.wait_group 1;" ::: "memory");
        } else {
            asm volatile("cp.async.wait_group 0;" ::: "memory");
        }
        __syncthreads();   // stage v visible to all

        const SmallV& sv = st->sv;
        const uint32_t sWh_b = smem_u32(&st->w[0][0]);
        const uint32_t sWl_b = smem_u32(&st->w[1][0]);

        // ---- row scalars for the 4 fragment rows this lane covers ----
        const float e = active ? noise[(long long)v * nsamp + n] * sv.std_ : 0.0f;
        float cr[4], er[4];
        #pragma unroll
        for (int q = 0; q < 4; q++) {
            cr[q] = __shfl_sync(0xffffffffu, carry, g + 8 * q);
            er[q] = __shfl_sync(0xffffffffu, e,     g + 8 * q);
        }

        // ---- layer 1 computed directly in A-fragment layout (no smem) ----
        uint32_t ah[2][4][4], al[2][4][4];
        #pragma unroll
        for (int kt = 0; kt < 4; kt++) {
            float4 wA = sv.l1w[8 * kt + l3];
            float2 bA = sv.l1b[8 * kt + l3];
            float4 wB = sv.l1w[8 * kt + l3 + 4];
            float2 bB = sv.l1b[8 * kt + l3 + 4];
            #pragma unroll
            for (int q = 0; q < 4; q++) {
                const int mt = q >> 1, idx = q & 1;
                float h0 = fmaxf(fmaf(cr[q], wA.x, fmaf(er[q], wA.z, bA.x)), 0.0f);
                float h1 = fmaxf(fmaf(cr[q], wA.y, fmaf(er[q], wA.w, bA.y)), 0.0f);
                float l0, l1;
                ah[mt][kt][idx] = split_hi_pair(h0, h1, l0, l1);
                al[mt][kt][idx] = pack_bf16x2(l0, l1);
                float h2 = fmaxf(fmaf(cr[q], wB.x, fmaf(er[q], wB.z, bB.x)), 0.0f);
                float h3 = fmaxf(fmaf(cr[q], wB.y, fmaf(er[q], wB.w, bB.y)), 0.0f);
                ah[mt][kt][2 + idx] = split_hi_pair(h2, h3, l0, l1);
                al[mt][kt][2 + idx] = pack_bf16x2(l0, l1);
            }
        }

        // ---- GEMM in jt-pairs: 4 independent acc chains, kt outer ----
        float p[2][2] = {{0, 0}, {0, 0}};   // [mt][row r / row r+8] epilogue partials

        #pragma unroll
        for (int jtp = 0; jtp < 4; jtp++) {
            uint32_t bh[2][8], bl[2][8];
            #pragma unroll
            for (int jt2 = 0; jt2 < 2; jt2++) {
                int jt = 2 * jtp + jt2;
                uint32_t nrowoff = (uint32_t)((jt * 8 + l7) * 128);
                uint32_t a0 = sWh_b + nrowoff + (uint32_t)(((0 + mi) ^ l7) * 16);
                uint32_t a1 = sWh_b + nrowoff + (uint32_t)(((4 + mi) ^ l7) * 16);
                ldmx4(bh[jt2][0], bh[jt2][1], bh[jt2][2], bh[jt2][3], a0);
                ldmx4(bh[jt2][4], bh[jt2][5], bh[jt2][6], bh[jt2][7], a1);
                uint32_t a2 = sWl_b + nrowoff + (uint32_t)(((0 + mi) ^ l7) * 16);
                uint32_t a3 = sWl_b + nrowoff + (uint32_t)(((4 + mi) ^ l7) * 16);
                ldmx4(bl[jt2][0], bl[jt2][1], bl[jt2][2], bl[jt2][3], a2);
                ldmx4(bl[jt2][4], bl[jt2][5], bl[jt2][6], bl[jt2][7], a3);
            }

            float acc[2][2][4];   // [jt2][mt][quad]
            #pragma unroll
            for (int jt2 = 0; jt2 < 2; jt2++)
                #pragma unroll
                for (int mt = 0; mt < 2; mt++)
                    #pragma unroll
                    for (int q = 0; q < 4; q++) acc[jt2][mt][q] = 0.0f;

            #pragma unroll
            for (int kt = 0; kt < 4; kt++) {
                #pragma unroll
                for (int jt2 = 0; jt2 < 2; jt2++)
                    #pragma unroll
                    for (int mt = 0; mt < 2; mt++)
                        mma_bf16(acc[jt2][mt], ah[mt][kt], bh[jt2][2 * kt], bh[jt2][2 * kt + 1]);
                #pragma unroll
                for (int jt2 = 0; jt2 < 2; jt2++)
                    #pragma unroll
                    for (int mt = 0; mt < 2; mt++)
                        mma_bf16(acc[jt2][mt], ah[mt][kt], bl[jt2][2 * kt], bl[jt2][2 * kt + 1]);
                #pragma unroll
                for (int jt2 = 0; jt2 < 2; jt2++)
                    #pragma unroll
                    for (int mt = 0; mt < 2; mt++)
                        mma_bf16(acc[jt2][mt], al[mt][kt], bh[jt2][2 * kt], bh[jt2][2 * kt + 1]);
            }

            // fold this jt-pair into epilogue partials
            #pragma unroll
            for (int jt2 = 0; jt2 < 2; jt2++) {
                int j0 = (2 * jtp + jt2) * 8 + 2 * l3;
                float2 bw0 = sv.b2w3[j0];
                float2 bw1 = sv.b2w3[j0 + 1];
                #pragma unroll
                for (int mt = 0; mt < 2; mt++) {
                    p[mt][0] = fmaf(fmaxf(acc[jt2][mt][0] + bw0.x, 0.0f), bw0.y, p[mt][0]);
                    p[mt][0] = fmaf(fmaxf(acc[jt2][mt][1] + bw1.x, 0.0f), bw1.y, p[mt][0]);
                    p[mt][1] = fmaf(fmaxf(acc[jt2][mt][2] + bw0.x, 0.0f), bw0.y, p[mt][1]);
                    p[mt][1] = fmaf(fmaxf(acc[jt2][mt][3] + bw1.x, 0.0f), bw1.y, p[mt][1]);
                }
            }
        }

        // ---- reduce across group-of-4 lanes, scatter carry back ----
        #pragma unroll
        for (int mt = 0; mt < 2; mt++)
            #pragma unroll
            for (int q = 0; q < 2; q++) {
                p[mt][q] += __shfl_xor_sync(0xffffffffu, p[mt][q], 1);
                p[mt][q] += __shfl_xor_sync(0xffffffffu, p[mt][q], 2);
            }
        if (l3 == 0) {
            int r = lane >> 2;                 // 0..7
            sCar[w * 32 + r]      = p[0][0];
            sCar[w * 32 + r + 8]  = p[0][1];
            sCar[w * 32 + r + 16] = p[1][0];
            sCar[w * 32 + r + 24] = p[1][1];
        }
        __syncwarp();
        carry = sCar[w * 32 + lane] + sv.b3;

        if (active) out[(long long)v * nsamp + n] = carry;

        __syncthreads();   // all warps done reading stage v before it is overwritten
    }
}

extern "C" void kernel_launch(void* const* d_in, const int* in_sizes, int n_in,
                              void* d_out, int out_size) {
    const float* noise = (const float*)d_in[0];
    const float* stds  = (const float*)d_in[1];
    const float* w0_1  = (const float*)d_in[2];
    const float* b0_1  = (const float*)d_in[3];
    const float* w0_2  = (const float*)d_in[4];
    const float* b0_2  = (const float*)d_in[5];
    const float* w0_3  = (const float*)d_in[6];
    const float* b0_3  = (const float*)d_in[7];
    const float* W1    = (const float*)d_in[8];
    const float* B1    = (const float*)d_in[9];
    const float* W2    = (const float*)d_in[10];
    const float* B2    = (const float*)d_in[11];
    const float* W3    = (const float*)d_in[12];
    const float* B3    = (const float*)d_in[13];

    const int nsamp = in_sizes[0] / NV;
    prep_kernel<<<NV, 256>>>(stds, w0_1, b0_1, w0_2, b0_2, w0_3, b0_3,
                             W1, B1, W2, B2, W3, B3);
    const int grid = (nsamp + TPB - 1) / TPB;
    ncm_hmma_kernel<<<grid, TPB>>>(noise, (float*)d_out, nsamp);
}